// round 15
// baseline (speedup 1.0000x reference)
#include <cuda_runtime.h>
#include <cuda_bf16.h>
#include <math.h>

static constexpr int IN_DIM  = 592;
static constexpr int W_NUMEL = 21760;
static constexpr int NT      = 256;     // 8 warps
static constexpr int ZT      = 64;      // batch rows per CTA (all blocks)

// ---- mma.sync m16n8k16 bf16, fp32 accumulate -------------------------------
__device__ __forceinline__ void mma_bf16(float* c, const unsigned* a, const unsigned* b) {
    asm volatile(
        "mma.sync.aligned.m16n8k16.row.col.f32.bf16.bf16.f32 "
        "{%0,%1,%2,%3}, {%4,%5,%6,%7}, {%8,%9}, {%0,%1,%2,%3};\n"
        : "+f"(c[0]), "+f"(c[1]), "+f"(c[2]), "+f"(c[3])
        : "r"(a[0]), "r"(a[1]), "r"(a[2]), "r"(a[3]), "r"(b[0]), "r"(b[1]));
}

// error-compensated bf16 split: v ~= h + l with ~2^-18 relative error
__device__ __forceinline__ void split_bf16(float v, __nv_bfloat16& h, __nv_bfloat16& l) {
    h = __float2bfloat16(v);
    l = __float2bfloat16(v - __bfloat162float(h));
}

// One irrep block as a GEMM: C[r,w] = sum_u A[r,u] * W[u,w],
//   r = zloc*DIM + i,  A[r,u] = pw * x[z, u*DIM+i]
// A (hi/lo bf16) staged row-major [M][LDA]; B staged transposed [w][u] for
// col-major fragments. LDA/2 = 4*odd (mod 32) -> all frag LDS.32 conflict-free.
// 3-term split MMA: C += Ah*Bh + Ah*Bl + Al*Bh.
template<int MUL, int DIM, int XOFF, int WOFF, int GM, int GN, int MW, int NW, int KC>
__device__ __forceinline__
void irrep_mma(const float* __restrict__ x,
               const float* __restrict__ wts,
               float* __restrict__ out,
               int batch, int bid, char* smem)
{
    constexpr int K    = MUL, N = MUL;
    constexpr int M    = GM * MW * 16;
    constexpr int RL   = MUL * DIM;     // x slice floats per row
    constexpr int LDA  = KC + 8;        // bf16 units; LDA/2 = 4*odd -> no conflicts
    constexpr int LDA4 = LDA / 2;       // 4B units
    constexpr int NPASS = K / KC;
    constexpr int CH   = KC * DIM;      // x columns per k-chunk (contiguous!)
    constexpr int CH4  = CH / 4;
    constexpr int LDN  = N + 2;         // C staging stride (floats)
    static_assert(M == ZT * DIM, "CTA row tile covers ZT batch rows");
    static_assert(GM * GN == NT / 32, "warp grid covers CTA");
    static_assert(NPASS * KC == K, "k-chunks cover K");
    static_assert((LDA4 % 8) == 4 && ((LDA4 / 4) & 1) == 1, "conflict-free pad");

    __nv_bfloat16* Ah = (__nv_bfloat16*)smem;
    __nv_bfloat16* Al = Ah + M * LDA;
    __nv_bfloat16* Bh = Al + M * LDA;
    __nv_bfloat16* Bl = Bh + N * LDA;
    const unsigned* A4h = (const unsigned*)Ah;
    const unsigned* A4l = (const unsigned*)Al;
    const unsigned* B4h = (const unsigned*)Bh;
    const unsigned* B4l = (const unsigned*)Bl;

    const int tid = threadIdx.x;
    const int z0  = bid * ZT;
    const int zc  = min(ZT, batch - z0);
    const float pw = 1.0f / sqrtf((float)MUL);

    const int lane = tid & 31, wp = tid >> 5;
    const int wm = wp % GM, wn = wp / GM;
    const int g = lane >> 2, t = lane & 3;

    float c[MW][NW][4] = {};

    for (int p = 0; p < NPASS; ++p) {
        __syncthreads();   // previous pass fully consumed

        // ---- stage A chunk: x cols [p*CH, p*CH+CH) are exactly u-chunk ----
        for (int idx = tid; idx < zc * CH4; idx += NT) {
            int zl = idx / CH4, q = idx - zl * CH4;
            float4 v = *(const float4*)&x[(size_t)(z0 + zl) * IN_DIM + XOFF + p * CH + 4 * q];
            float vv[4] = {v.x, v.y, v.z, v.w};
            #pragma unroll
            for (int e = 0; e < 4; ++e) {
                int cc = 4 * q + e;
                int ul = cc / DIM, i = cc - ul * DIM;
                int r  = zl * DIM + i;
                __nv_bfloat16 h, l;
                split_bf16(vv[e] * pw, h, l);
                Ah[r * LDA + ul] = h;
                Al[r * LDA + ul] = l;
            }
        }
        // ---- stage B chunk transposed: Bs[w][u] ----------------------------
        for (int idx = tid; idx < (KC * N) / 4; idx += NT) {
            int ul = (4 * idx) / N, w = (4 * idx) % N;
            float4 v = *(const float4*)&wts[WOFF + (size_t)(p * KC + ul) * N + w];
            float vv[4] = {v.x, v.y, v.z, v.w};
            #pragma unroll
            for (int e = 0; e < 4; ++e) {
                __nv_bfloat16 h, l;
                split_bf16(vv[e], h, l);
                Bh[(w + e) * LDA + ul] = h;
                Bl[(w + e) * LDA + ul] = l;
            }
        }
        __syncthreads();

        // ---- k-steps of 16 --------------------------------------------------
        #pragma unroll
        for (int ks = 0; ks < KC / 16; ++ks) {
            const int kb4 = ks * 8 + t;
            unsigned bhf[NW][2], blf[NW][2];
            #pragma unroll
            for (int ni = 0; ni < NW; ++ni) {
                int a = ((wn * NW + ni) * 8 + g) * LDA4 + kb4;
                bhf[ni][0] = B4h[a]; bhf[ni][1] = B4h[a + 4];
                blf[ni][0] = B4l[a]; blf[ni][1] = B4l[a + 4];
            }
            #pragma unroll
            for (int mi = 0; mi < MW; ++mi) {
                int a0 = ((wm * MW + mi) * 16 + g) * LDA4 + kb4;
                int a1 = a0 + 8 * LDA4;
                unsigned ah[4] = {A4h[a0], A4h[a1], A4h[a0 + 4], A4h[a1 + 4]};
                unsigned al[4] = {A4l[a0], A4l[a1], A4l[a0 + 4], A4l[a1 + 4]};
                #pragma unroll
                for (int ni = 0; ni < NW; ++ni) {
                    mma_bf16(c[mi][ni], ah, bhf[ni]);
                    mma_bf16(c[mi][ni], ah, blf[ni]);
                    mma_bf16(c[mi][ni], al, bhf[ni]);
                }
            }
        }
    }
    __syncthreads();   // main-loop smem reads done; reuse as C staging

    // ---- stage C [r][w] in smem, then coalesced global store ---------------
    float* Cs = (float*)smem;
    #pragma unroll
    for (int mi = 0; mi < MW; ++mi) {
        int r0 = (wm * MW + mi) * 16;
        #pragma unroll
        for (int ni = 0; ni < NW; ++ni) {
            int nb = (wn * NW + ni) * 8;
            *(float2*)&Cs[(r0 + g    ) * LDN + nb + 2 * t] = make_float2(c[mi][ni][0], c[mi][ni][1]);
            *(float2*)&Cs[(r0 + g + 8) * LDN + nb + 2 * t] = make_float2(c[mi][ni][2], c[mi][ni][3]);
        }
    }
    __syncthreads();

    for (int idx = tid; idx < zc * RL; idx += NT) {
        int zl = idx / RL, cc = idx - zl * RL;
        int w = cc / DIM, i = cc - w * DIM;
        out[(size_t)(z0 + zl) * IN_DIM + XOFF + cc] = Cs[(zl * DIM + i) * LDN + w];
    }
}

// ---- fused dispatch (type interleaved for SM load balance) ------------------
__global__ __launch_bounds__(NT)
void fused_mma_kernel(const float* __restrict__ x,
                      const float* __restrict__ wts,
                      float* __restrict__ out,
                      int batch)
{
    extern __shared__ __align__(16) char smem[];
    const int type = blockIdx.x & 3;
    const int bid  = blockIdx.x >> 2;

    //            MUL DIM XOFF  WOFF GM GN MW NW  KC
    if (type == 0)
        irrep_mma<128, 1,   0,     0, 2, 4, 2, 4, 64>(x, wts, out, batch, bid, smem); // M64 N128 K128, 2 passes, 55.3KB
    else if (type == 1)
        irrep_mma< 64, 3, 128, 16384, 4, 2, 3, 4, 64>(x, wts, out, batch, bid, smem); // M192 N64 K64, 73.7KB
    else if (type == 2)
        irrep_mma< 32, 5, 320, 20480, 4, 2, 5, 2, 32>(x, wts, out, batch, bid, smem); // M320 N32 K32, 56.3KB
    else
        irrep_mma< 16, 7, 480, 21504, 4, 2, 7, 1, 16>(x, wts, out, batch, bid, smem); // M448 N16 K16, 44.5KB
}

extern "C" void kernel_launch(void* const* d_in, const int* in_sizes, int n_in,
                              void* d_out, int out_size)
{
    (void)out_size;
    const float* x = (const float*)d_in[0];
    const float* w = (const float*)d_in[1];
    int xsz = in_sizes[0];
    if (n_in >= 2 && in_sizes[0] == W_NUMEL) {   // robust to input ordering
        x = (const float*)d_in[1];
        w = (const float*)d_in[0];
        xsz = in_sizes[1];
    }
    float* out = (float*)d_out;
    const int batch = xsz / IN_DIM;

    const int g = (batch + ZT - 1) / ZT;
    const int grid = 4 * g;

    // max smem over paths = block 1: (192+64)*72 bf16 * 2 arrays = 73728 B
    const int sm = 73728;
    cudaFuncSetAttribute(fused_mma_kernel,
                         cudaFuncAttributeMaxDynamicSharedMemorySize, sm);
    fused_mma_kernel<<<grid, NT, sm>>>(x, w, out, batch);
}

// round 16
// speedup vs baseline: 1.3099x; 1.3099x over previous
#include <cuda_runtime.h>
#include <cuda_bf16.h>

static constexpr int IN_DIM  = 592;
static constexpr int W_NUMEL = 21760;
static constexpr int NT      = 256;     // 8 warps

// ---- mma.sync m16n8k16 bf16, fp32 accumulate -------------------------------
__device__ __forceinline__ void mma_bf16(float* c, const unsigned* a, const unsigned* b) {
    asm volatile(
        "mma.sync.aligned.m16n8k16.row.col.f32.bf16.bf16.f32 "
        "{%0,%1,%2,%3}, {%4,%5,%6,%7}, {%8,%9}, {%0,%1,%2,%3};\n"
        : "+f"(c[0]), "+f"(c[1]), "+f"(c[2]), "+f"(c[3])
        : "r"(a[0]), "r"(a[1]), "r"(a[2]), "r"(a[3]), "r"(b[0]), "r"(b[1]));
}
__device__ __forceinline__ void ldsm4t(unsigned* r, unsigned a) {
    asm volatile("ldmatrix.sync.aligned.m8n8.x4.trans.shared.b16 {%0,%1,%2,%3}, [%4];"
                 : "=r"(r[0]), "=r"(r[1]), "=r"(r[2]), "=r"(r[3]) : "r"(a));
}
__device__ __forceinline__ void ldsm2(unsigned* r, unsigned a) {
    asm volatile("ldmatrix.sync.aligned.m8n8.x2.shared.b16 {%0,%1}, [%2];"
                 : "=r"(r[0]), "=r"(r[1]) : "r"(a));
}
// pack two floats (lo, hi) into bf16x2 with RN rounding
__device__ __forceinline__ unsigned bf2(float lo, float hi) {
    unsigned r;
    asm("cvt.rn.bf16x2.f32 %0, %1, %2;" : "=r"(r) : "f"(hi), "f"(lo));
    return r;
}

// One irrep block as GEMM  D[m=w][n=r] = sum_k WT[w,u] * X[r,u],  r = zl*DIM+i.
//  * W staged [u][w] (natural, coalesced STS.64, pw folded) -> a-frags via
//    ldmatrix.x4.trans; X staged [r][u] (natural) -> b-frags via ldmatrix.x2.
//  * row strides LDX/LDW are odd multiples of 16B -> conflict-free ldmatrix.
//  * X staged ONCE (full K); only W chunked over K (L2-hot).
//  * 3-term bf16 split: D += WhXh + WlXh + WhXl  (rel err ~4e-6).
template<int MUL, int DIM, int XOFF, int WOFF, int ZT,
         int GM, int GN, int MW, int NW, int KC>
__device__ __forceinline__
void irrep_mma(const float* __restrict__ x, const float* __restrict__ wts,
               float* __restrict__ out, int batch, int bid, char* smem)
{
    constexpr int K   = MUL;            // k-axis: u
    constexpr int M   = MUL;            // m-axis: w
    constexpr int N   = ZT * DIM;       // n-axis: r
    constexpr int LDX = K + 8;          // bf16 row stride (odd multiple of 16B)
    constexpr int LDW = M + 8;
    constexpr int NP  = K / KC;
    constexpr int RL  = MUL * DIM;
    constexpr int RL4 = RL / 4;
    constexpr int LDC = N + 2;          // fp32 C staging stride (8B-aligned f2)
    static_assert(GM * GN == NT / 32, "8 warps");
    static_assert(GM * MW * 16 == M, "m tiling");
    static_assert(GN * NW * 8 == N, "n tiling");
    static_assert(NP * KC == K, "k chunks");
    static_assert((((LDX * 2) / 16) & 1) == 1 && (((LDW * 2) / 16) & 1) == 1,
                  "ldmatrix conflict-free strides");

    __nv_bfloat16* Xh = (__nv_bfloat16*)smem;
    __nv_bfloat16* Xl = Xh + N * LDX;
    __nv_bfloat16* Wh = Xl + N * LDX;
    __nv_bfloat16* Wl = Wh + KC * LDW;

    const int tid = threadIdx.x;
    const int z0  = bid * ZT;
    const int zc  = min(ZT, batch - z0);
    const float pw = rsqrtf((float)MUL);

    // ---- stage X once (raw fp32 -> hi/lo bf16; pw lives in W) --------------
    for (int idx = tid; idx < zc * RL4; idx += NT) {
        int zl = idx / RL4, q = idx - zl * RL4;
        float4 v = *(const float4*)&x[(size_t)(z0 + zl) * IN_DIM + XOFF + 4 * q];
        float vv[4] = {v.x, v.y, v.z, v.w};
        if (DIM == 1) {                 // packed, coalesced STS.64
            __nv_bfloat16 h[4]; float l[4];
            #pragma unroll
            for (int e = 0; e < 4; ++e) {
                h[e] = __float2bfloat16(vv[e]);
                l[e] = vv[e] - __bfloat162float(h[e]);
            }
            uint2 ph = make_uint2(
                (unsigned)__bfloat16_as_ushort(h[0]) | ((unsigned)__bfloat16_as_ushort(h[1]) << 16),
                (unsigned)__bfloat16_as_ushort(h[2]) | ((unsigned)__bfloat16_as_ushort(h[3]) << 16));
            uint2 pl = make_uint2(bf2(l[0], l[1]), bf2(l[2], l[3]));
            *(uint2*)&Xh[zl * LDX + 4 * q] = ph;
            *(uint2*)&Xl[zl * LDX + 4 * q] = pl;
        } else {
            #pragma unroll
            for (int e = 0; e < 4; ++e) {
                int cc = 4 * q + e;
                int u = cc / DIM, i = cc - u * DIM;
                int r = zl * DIM + i;
                __nv_bfloat16 h = __float2bfloat16(vv[e]);
                Xh[r * LDX + u] = h;
                Xl[r * LDX + u] = __float2bfloat16(vv[e] - __bfloat162float(h));
            }
        }
    }
    for (int idx = zc * DIM * LDX + tid; idx < N * LDX; idx += NT) {
        Xh[idx] = __ushort_as_bfloat16(0);     // tail CTA: zero padding rows
        Xl[idx] = __ushort_as_bfloat16(0);
    }

    // ---- thread/warp mapping -------------------------------------------------
    const int lane = tid & 31, wp = tid >> 5;
    const int wm = wp % GM, wn = wp / GM;
    const int ua = (lane & 7) + ((lane >> 4) << 3);  // a-frag row (u) offset
    const int wa = (lane & 8);                       // a-frag col (w) offset
    const int rb = (lane & 7);                       // b-frag row (r) offset
    const int kb = (lane & 8);                       // b-frag col (k) offset
    const unsigned xh_s = (unsigned)__cvta_generic_to_shared(Xh);
    const unsigned xl_s = (unsigned)__cvta_generic_to_shared(Xl);
    const unsigned wh_s = (unsigned)__cvta_generic_to_shared(Wh);
    const unsigned wl_s = (unsigned)__cvta_generic_to_shared(Wl);

    float c[MW][NW][4] = {};

    // ---- K passes: stage W chunk (pw folded), then tensor compute ----------
    for (int p = 0; p < NP; ++p) {
        if (p) __syncthreads();          // prior pass's W reads complete
        for (int idx = tid; idx < KC * M / 4; idx += NT) {
            int ul = (4 * idx) / M, wc = (4 * idx) % M;
            float4 v = *(const float4*)&wts[WOFF + (size_t)(p * KC + ul) * M + wc];
            float s[4] = {v.x * pw, v.y * pw, v.z * pw, v.w * pw};
            __nv_bfloat16 h[4]; float l[4];
            #pragma unroll
            for (int e = 0; e < 4; ++e) {
                h[e] = __float2bfloat16(s[e]);
                l[e] = s[e] - __bfloat162float(h[e]);
            }
            uint2 ph = make_uint2(
                (unsigned)__bfloat16_as_ushort(h[0]) | ((unsigned)__bfloat16_as_ushort(h[1]) << 16),
                (unsigned)__bfloat16_as_ushort(h[2]) | ((unsigned)__bfloat16_as_ushort(h[3]) << 16));
            uint2 pl = make_uint2(bf2(l[0], l[1]), bf2(l[2], l[3]));
            *(uint2*)&Wh[ul * LDW + wc] = ph;
            *(uint2*)&Wl[ul * LDW + wc] = pl;
        }
        __syncthreads();                 // also covers X staging before p==0

        #pragma unroll
        for (int ks = 0; ks < KC / 16; ++ks) {
            unsigned ah[MW][4], al[MW][4];
            #pragma unroll
            for (int mi = 0; mi < MW; ++mi) {
                unsigned off = 2u * ((ks * 16 + ua) * LDW + (wm * MW + mi) * 16 + wa);
                ldsm4t(ah[mi], wh_s + off);
                ldsm4t(al[mi], wl_s + off);
            }
            #pragma unroll
            for (int ni = 0; ni < NW; ++ni) {
                unsigned off = 2u * (((wn * NW + ni) * 8 + rb) * LDX + p * KC + ks * 16 + kb);
                unsigned bh[2], bl[2];
                ldsm2(bh, xh_s + off);
                ldsm2(bl, xl_s + off);
                #pragma unroll
                for (int mi = 0; mi < MW; ++mi) {
                    mma_bf16(c[mi][ni], ah[mi], bh);
                    mma_bf16(c[mi][ni], al[mi], bh);
                    mma_bf16(c[mi][ni], ah[mi], bl);
                }
            }
        }
    }
    __syncthreads();    // all smem reads done; reuse as C staging

    // ---- stage D[w][r] in smem, then coalesced global store ----------------
    float* Cs = (float*)smem;
    const int g = lane >> 2, t = lane & 3;
    #pragma unroll
    for (int mi = 0; mi < MW; ++mi) {
        int m0 = (wm * MW + mi) * 16;
        #pragma unroll
        for (int ni = 0; ni < NW; ++ni) {
            int n0 = (wn * NW + ni) * 8;
            *(float2*)&Cs[(m0 + g    ) * LDC + n0 + 2 * t] = make_float2(c[mi][ni][0], c[mi][ni][1]);
            *(float2*)&Cs[(m0 + g + 8) * LDC + n0 + 2 * t] = make_float2(c[mi][ni][2], c[mi][ni][3]);
        }
    }
    __syncthreads();

    for (int idx = tid; idx < zc * RL; idx += NT) {
        int zl = idx / RL, cc = idx - zl * RL;
        int w = cc / DIM, i = cc - w * DIM;
        out[(size_t)(z0 + zl) * IN_DIM + XOFF + cc] = Cs[w * LDC + zl * DIM + i];
    }
}

// ---- fused dispatch ----------------------------------------------------------
__global__ __launch_bounds__(NT, 2)
void fused_mma2_kernel(const float* __restrict__ x,
                       const float* __restrict__ wts,
                       float* __restrict__ out,
                       int batch)
{
    extern __shared__ __align__(16) char smem[];
    const int g0 = (batch + 63) >> 6;
    const int g1 = (batch + 31) >> 5;
    const int g2 = (batch + 31) >> 5;
    int bid = blockIdx.x;

    //            MUL DIM XOFF  WOFF  ZT GM GN MW NW  KC      smem
    if (bid < g0)
        irrep_mma<128, 1,   0,     0, 64, 4, 2, 2, 4, 64>(x, wts, out, batch, bid, smem);       // 69.6KB
    else if ((bid -= g0) < g1)
        irrep_mma< 64, 3, 128, 16384, 32, 2, 4, 2, 3, 64>(x, wts, out, batch, bid, smem);       // 46.1KB
    else if ((bid -= g1) < g2)
        irrep_mma< 32, 5, 320, 20480, 32, 2, 4, 1, 5, 32>(x, wts, out, batch, bid, smem);       // 30.7KB
    else
        irrep_mma< 16, 7, 480, 21504, 64, 1, 8, 1, 7, 16>(x, wts, out, batch, bid - g2, smem);  // 44.5KB
}

extern "C" void kernel_launch(void* const* d_in, const int* in_sizes, int n_in,
                              void* d_out, int out_size)
{
    (void)out_size;
    const float* x = (const float*)d_in[0];
    const float* w = (const float*)d_in[1];
    int xsz = in_sizes[0];
    if (n_in >= 2 && in_sizes[0] == W_NUMEL) {   // robust to input ordering
        x = (const float*)d_in[1];
        w = (const float*)d_in[0];
        xsz = in_sizes[1];
    }
    float* out = (float*)d_out;
    const int batch = xsz / IN_DIM;

    const int g0 = (batch + 63) >> 6;
    const int g1 = (batch + 31) >> 5;
    const int g2 = (batch + 31) >> 5;
    const int g3 = (batch + 63) >> 6;
    const int grid = g0 + g1 + g2 + g3;

    const int sm = 69632;   // max over paths (block 0)
    cudaFuncSetAttribute(fused_mma2_kernel,
                         cudaFuncAttributeMaxDynamicSharedMemorySize, sm);
    fused_mma2_kernel<<<grid, NT, sm>>>(x, w, out, batch);
}

// round 17
// speedup vs baseline: 1.4043x; 1.0721x over previous
#include <cuda_runtime.h>
#include <cuda_bf16.h>

static constexpr int IN_DIM  = 592;
static constexpr int W_NUMEL = 21760;
static constexpr int NT      = 256;     // 8 warps

// ---- W fragment buffer: 85 frags (64+16+4+1) x 1024B (512B hi + 512B lo) ---
static __device__ __align__(16) unsigned g_wfrag[85 * 256];

// ---- mma.sync m16n8k16 bf16, fp32 accumulate -------------------------------
__device__ __forceinline__ void mma_bf16(float* c, const unsigned* a, const unsigned* b) {
    asm volatile(
        "mma.sync.aligned.m16n8k16.row.col.f32.bf16.bf16.f32 "
        "{%0,%1,%2,%3}, {%4,%5,%6,%7}, {%8,%9}, {%0,%1,%2,%3};\n"
        : "+f"(c[0]), "+f"(c[1]), "+f"(c[2]), "+f"(c[3])
        : "r"(a[0]), "r"(a[1]), "r"(a[2]), "r"(a[3]), "r"(b[0]), "r"(b[1]));
}
__device__ __forceinline__ void ldsm2(unsigned* r, unsigned a) {
    asm volatile("ldmatrix.sync.aligned.m8n8.x2.shared.b16 {%0,%1}, [%2];"
                 : "=r"(r[0]), "=r"(r[1]) : "r"(a));
}
// pack two floats (lo half, hi half) into bf16x2 with RN rounding
__device__ __forceinline__ unsigned bf2(float lo, float hi) {
    unsigned r;
    asm("cvt.rn.bf16x2.f32 %0, %1, %2;" : "=r"(r) : "f"(hi), "f"(lo));
    return r;
}

// ---- prep: w -> fragment-linear hi/lo bf16 planes, pw folded ----------------
// A-operand lane map for m16n8k16 (row-major A = WT, A[m=w][k=u]):
//   reg r (0..3): m = mt*16 + g + (r&1)*8,  k = ks*16 + 2t + (r>>1)*8, pair (k,k+1)
__global__ void prep_wfrag_kernel(const float* __restrict__ wts) {
    int e = blockIdx.x * blockDim.x + threadIdx.x;
    if (e >= 85 * 32) return;
    int fi = e >> 5, lane = e & 31;
    int ks, mt, MULt, WOFFt;
    if (fi < 64)      { ks = fi >> 3;            mt = fi & 7;        MULt = 128; WOFFt = 0;     }
    else if (fi < 80) { int f = fi - 64; ks = f >> 2; mt = f & 3;    MULt = 64;  WOFFt = 16384; }
    else if (fi < 84) { int f = fi - 80; ks = f >> 1; mt = f & 1;    MULt = 32;  WOFFt = 20480; }
    else              { ks = 0;                  mt = 0;             MULt = 16;  WOFFt = 21504; }
    const float pw = rsqrtf((float)MULt);
    const int g = lane >> 2, t = lane & 3;
    unsigned hi[4], lo[4];
    #pragma unroll
    for (int r = 0; r < 4; ++r) {
        int m = mt * 16 + g + (r & 1) * 8;
        int k = ks * 16 + 2 * t + (r >> 1) * 8;
        float v0 = wts[WOFFt + (size_t)k * MULt + m] * pw;
        float v1 = wts[WOFFt + (size_t)(k + 1) * MULt + m] * pw;
        __nv_bfloat16 h0 = __float2bfloat16(v0), h1 = __float2bfloat16(v1);
        hi[r] = (unsigned)__bfloat16_as_ushort(h0) | ((unsigned)__bfloat16_as_ushort(h1) << 16);
        lo[r] = bf2(v0 - __bfloat162float(h0), v1 - __bfloat162float(h1));
    }
    *(uint4*)&g_wfrag[fi * 256 + lane * 4]       = make_uint4(hi[0], hi[1], hi[2], hi[3]);
    *(uint4*)&g_wfrag[fi * 256 + 128 + lane * 4] = make_uint4(lo[0], lo[1], lo[2], lo[3]);
}

// One irrep block as GEMM  D[m=w][n=r] = sum_k WT[w,u] * X[r,u],  r = zl*DIM+i.
//  * W: fragment-linear LDG.128 from g_wfrag (no smem, no conversion, no sync)
//  * X: staged once in smem as hi/lo bf16 (odd-16B row stride -> conflict-free
//    ldmatrix), b-frags via ldsm2 (layout verified in round 15)
//  * 3-term bf16 split: D += Wh*Xh + Wl*Xh + Wh*Xl  (rel err ~4.5e-6)
template<int MUL, int DIM, int XOFF, int ZT, int GM, int GN, int MW, int NW, int FBASE>
__device__ __forceinline__
void irrep_mma(const float* __restrict__ x, float* __restrict__ out,
               int batch, int bid, char* smem)
{
    constexpr int K   = MUL, M = MUL;
    constexpr int N   = ZT * DIM;
    constexpr int LDX = K + 8;          // bf16 row stride (odd multiple of 16B)
    constexpr int NKS = K / 16, MT = M / 16;
    constexpr int RL  = MUL * DIM, RL4 = RL / 4;
    constexpr int LDC = N + 2;
    static_assert(GM * GN == NT / 32, "8 warps");
    static_assert(GM * MW * 16 == M && GN * NW * 8 == N, "tiling");
    static_assert((((LDX * 2) / 16) & 1) == 1, "ldmatrix conflict-free stride");

    __nv_bfloat16* Xh = (__nv_bfloat16*)smem;
    __nv_bfloat16* Xl = Xh + N * LDX;

    const int tid = threadIdx.x;
    const int z0  = bid * ZT;
    const int zc  = min(ZT, batch - z0);

    // ---- stage X once (fp32 -> hi/lo bf16; pw lives in W frags) ------------
    for (int idx = tid; idx < zc * RL4; idx += NT) {
        int zl = idx / RL4, q = idx - zl * RL4;
        float4 v = *(const float4*)&x[(size_t)(z0 + zl) * IN_DIM + XOFF + 4 * q];
        float vv[4] = {v.x, v.y, v.z, v.w};
        if (DIM == 1) {                 // packed, coalesced STS.64
            __nv_bfloat16 h[4]; float l[4];
            #pragma unroll
            for (int e = 0; e < 4; ++e) {
                h[e] = __float2bfloat16(vv[e]);
                l[e] = vv[e] - __bfloat162float(h[e]);
            }
            uint2 ph = make_uint2(
                (unsigned)__bfloat16_as_ushort(h[0]) | ((unsigned)__bfloat16_as_ushort(h[1]) << 16),
                (unsigned)__bfloat16_as_ushort(h[2]) | ((unsigned)__bfloat16_as_ushort(h[3]) << 16));
            uint2 pl = make_uint2(bf2(l[0], l[1]), bf2(l[2], l[3]));
            *(uint2*)&Xh[zl * LDX + 4 * q] = ph;
            *(uint2*)&Xl[zl * LDX + 4 * q] = pl;
        } else {
            #pragma unroll
            for (int e = 0; e < 4; ++e) {
                int cc = 4 * q + e;
                int u = cc / DIM, i = cc - u * DIM;
                int r = zl * DIM + i;
                __nv_bfloat16 h = __float2bfloat16(vv[e]);
                Xh[r * LDX + u] = h;
                Xl[r * LDX + u] = __float2bfloat16(vv[e] - __bfloat162float(h));
            }
        }
    }
    for (int idx = zc * DIM * LDX + tid; idx < N * LDX; idx += NT) {
        Xh[idx] = __ushort_as_bfloat16(0);   // tail CTA: zero padding rows
        Xl[idx] = __ushort_as_bfloat16(0);
    }
    __syncthreads();

    // ---- thread/warp mapping -------------------------------------------------
    const int lane = tid & 31, wp = tid >> 5;
    const int wm = wp % GM, wn = wp / GM;
    const int rb = (lane & 7);          // b-frag row (r) offset
    const int kb = (lane & 8);          // b-frag col (k) offset
    const unsigned xh_s = (unsigned)__cvta_generic_to_shared(Xh);
    const unsigned xl_s = (unsigned)__cvta_generic_to_shared(Xl);
    const uint4* __restrict__ WF = reinterpret_cast<const uint4*>(g_wfrag);

    float c[MW][NW][4] = {};

    #pragma unroll
    for (int ks = 0; ks < NKS; ++ks) {
        uint4 ah[MW], al[MW];
        #pragma unroll
        for (int mi = 0; mi < MW; ++mi) {      // contiguous 512B warp LDG.128
            int fi = FBASE + ks * MT + (wm * MW + mi);
            ah[mi] = __ldg(&WF[fi * 64 + lane]);
            al[mi] = __ldg(&WF[fi * 64 + 32 + lane]);
        }
        #pragma unroll
        for (int ni = 0; ni < NW; ++ni) {
            unsigned off = 2u * (((wn * NW + ni) * 8 + rb) * LDX + ks * 16 + kb);
            unsigned bh[2], bl[2];
            ldsm2(bh, xh_s + off);
            ldsm2(bl, xl_s + off);
            #pragma unroll
            for (int mi = 0; mi < MW; ++mi) {
                mma_bf16(c[mi][ni], (const unsigned*)&ah[mi], bh);
                mma_bf16(c[mi][ni], (const unsigned*)&al[mi], bh);
                mma_bf16(c[mi][ni], (const unsigned*)&ah[mi], bl);
            }
        }
    }
    __syncthreads();    // all X reads done; reuse smem as C staging

    // ---- stage D[w][r] in smem, then coalesced global store ----------------
    float* Cs = (float*)smem;
    const int g = lane >> 2, t = lane & 3;
    #pragma unroll
    for (int mi = 0; mi < MW; ++mi) {
        int m0 = (wm * MW + mi) * 16;
        #pragma unroll
        for (int ni = 0; ni < NW; ++ni) {
            int n0 = (wn * NW + ni) * 8;
            *(float2*)&Cs[(m0 + g    ) * LDC + n0 + 2 * t] = make_float2(c[mi][ni][0], c[mi][ni][1]);
            *(float2*)&Cs[(m0 + g + 8) * LDC + n0 + 2 * t] = make_float2(c[mi][ni][2], c[mi][ni][3]);
        }
    }
    __syncthreads();

    for (int idx = tid; idx < zc * RL; idx += NT) {
        int zl = idx / RL, cc = idx - zl * RL;
        int w = cc / DIM, i = cc - w * DIM;
        out[(size_t)(z0 + zl) * IN_DIM + XOFF + cc] = Cs[w * LDC + zl * DIM + i];
    }
}

// ---- fused dispatch ----------------------------------------------------------
__global__ __launch_bounds__(NT, 2)
void fused_mma3_kernel(const float* __restrict__ x,
                       float* __restrict__ out,
                       int batch)
{
    extern __shared__ __align__(16) char smem[];
    const int g0 = (batch + 63) >> 6;
    const int g1 = (batch + 31) >> 5;
    const int g2 = (batch + 31) >> 5;
    int bid = blockIdx.x;

    //            MUL DIM XOFF  ZT GM GN MW NW FBASE    smem
    if (bid < g0)
        irrep_mma<128, 1,   0, 64, 4, 2, 2, 4,  0>(x, out, batch, bid, smem);       // 34.8KB
    else if ((bid -= g0) < g1)
        irrep_mma< 64, 3, 128, 32, 2, 4, 2, 3, 64>(x, out, batch, bid, smem);       // 27.6KB
    else if ((bid -= g1) < g2)
        irrep_mma< 32, 5, 320, 32, 2, 4, 1, 5, 80>(x, out, batch, bid, smem);       // 25.6KB
    else
        irrep_mma< 16, 7, 480, 64, 1, 8, 1, 7, 84>(x, out, batch, bid - g2, smem);  // 43.0KB
}

extern "C" void kernel_launch(void* const* d_in, const int* in_sizes, int n_in,
                              void* d_out, int out_size)
{
    (void)out_size;
    const float* x = (const float*)d_in[0];
    const float* w = (const float*)d_in[1];
    int xsz = in_sizes[0];
    if (n_in >= 2 && in_sizes[0] == W_NUMEL) {   // robust to input ordering
        x = (const float*)d_in[1];
        w = (const float*)d_in[0];
        xsz = in_sizes[1];
    }
    float* out = (float*)d_out;
    const int batch = xsz / IN_DIM;

    // 1) hoist W conversion + fragment layout (once per call, ~3us)
    prep_wfrag_kernel<<<(85 * 32 + NT - 1) / NT, NT>>>(w);

    // 2) main fused kernel
    const int g0 = (batch + 63) >> 6;
    const int g1 = (batch + 31) >> 5;
    const int g2 = (batch + 31) >> 5;
    const int g3 = (batch + 63) >> 6;
    const int grid = g0 + g1 + g2 + g3;

    const int sm = 43008;   // max over paths (block 3)
    cudaFuncSetAttribute(fused_mma3_kernel,
                         cudaFuncAttributeMaxDynamicSharedMemorySize, sm);
    fused_mma3_kernel<<<grid, NT, sm>>>(x, out, batch);
}